// round 1
// baseline (speedup 1.0000x reference)
#include <cuda_runtime.h>
#include <math.h>

// Problem constants
#define BATCH 4
#define LQ 1024
#define LK 2048
#define DIMM 1024
#define NH 16
#define DH 64
#define FF 4096

#define MQ (BATCH * LQ)   // 4096 query rows
#define MC (BATCH * LK)   // 8192 context rows

// Scratch (allocation-free rule: __device__ globals)
__device__ float g_Q[MQ * DIMM];     // 16 MB
__device__ float g_K[MC * DIMM];     // 32 MB
__device__ float g_V[MC * DIMM];     // 32 MB
__device__ float g_O[MQ * DIMM];     // 16 MB
__device__ float g_X1[MQ * DIMM];    // 16 MB
__device__ float g_Hf[MQ * FF];      // 64 MB

__device__ __forceinline__ float gelu_exact(float x) {
    return 0.5f * x * (1.0f + erff(x * 0.70710678118654752f));
}

// ---------------------------------------------------------------------------
// SGEMM: C[M,N] = A[M,K] @ B[K,N]  (+ epilogue)
// 128x128 CTA tile, BK=8, 256 threads, 8x8 accumulator per thread.
// EPI: 0 = plain, 1 = +bias +residual, 2 = gelu(acc + bias)
// ---------------------------------------------------------------------------
template <int EPI>
__global__ __launch_bounds__(256) void sgemm_kernel(
    const float* __restrict__ A, const float* __restrict__ B,
    const float* __restrict__ bias, const float* __restrict__ res,
    float* __restrict__ C, int M, int N, int K)
{
    __shared__ float As[8][132];  // +4 pad: kills A-store conflicts, keeps 16B align
    __shared__ float Bs[8][132];

    const int tid = threadIdx.x;
    const int tx = tid & 15;      // 0..15  (column group)
    const int ty = tid >> 4;      // 0..15  (row group)
    const int rowBase = blockIdx.y * 128;
    const int colBase = blockIdx.x * 128;

    // A tile loader: thread -> (row, 4 k-values)
    const int ar = tid >> 1;           // 0..127
    const int ac = (tid & 1) * 4;      // 0 or 4
    // B tile loader: thread -> (k-row, 4 columns)
    const int br = tid >> 5;           // 0..7
    const int bc = (tid & 31) * 4;     // 0..124

    const float* Aptr = A + (size_t)(rowBase + ar) * K + ac;
    const float* Bptr = B + (size_t)br * N + colBase + bc;

    float acc[8][8];
#pragma unroll
    for (int i = 0; i < 8; i++)
#pragma unroll
        for (int j = 0; j < 8; j++) acc[i][j] = 0.0f;

    for (int k0 = 0; k0 < K; k0 += 8) {
        float4 av = *(const float4*)(Aptr + k0);
        float4 bv = *(const float4*)(Bptr + (size_t)k0 * N);
        As[ac + 0][ar] = av.x;
        As[ac + 1][ar] = av.y;
        As[ac + 2][ar] = av.z;
        As[ac + 3][ar] = av.w;
        *(float4*)&Bs[br][bc] = bv;
        __syncthreads();

#pragma unroll
        for (int kk = 0; kk < 8; kk++) {
            float a[8], b[8];
            *(float4*)&a[0] = *(const float4*)&As[kk][ty * 8];
            *(float4*)&a[4] = *(const float4*)&As[kk][ty * 8 + 4];
            *(float4*)&b[0] = *(const float4*)&Bs[kk][tx * 8];
            *(float4*)&b[4] = *(const float4*)&Bs[kk][tx * 8 + 4];
#pragma unroll
            for (int i = 0; i < 8; i++)
#pragma unroll
                for (int j = 0; j < 8; j++)
                    acc[i][j] = fmaf(a[i], b[j], acc[i][j]);
        }
        __syncthreads();
    }

    const int row0 = rowBase + ty * 8;
    const int col0 = colBase + tx * 8;
#pragma unroll
    for (int i = 0; i < 8; i++) {
        const int row = row0 + i;
#pragma unroll
        for (int j4 = 0; j4 < 2; j4++) {
            const int col = col0 + j4 * 4;
            float4 v;
            v.x = acc[i][j4 * 4 + 0];
            v.y = acc[i][j4 * 4 + 1];
            v.z = acc[i][j4 * 4 + 2];
            v.w = acc[i][j4 * 4 + 3];
            if (EPI == 1) {
                float4 bb = *(const float4*)&bias[col];
                float4 rr = *(const float4*)&res[(size_t)row * N + col];
                v.x += bb.x + rr.x;
                v.y += bb.y + rr.y;
                v.z += bb.z + rr.z;
                v.w += bb.w + rr.w;
            } else if (EPI == 2) {
                float4 bb = *(const float4*)&bias[col];
                v.x = gelu_exact(v.x + bb.x);
                v.y = gelu_exact(v.y + bb.y);
                v.z = gelu_exact(v.z + bb.z);
                v.w = gelu_exact(v.w + bb.w);
            }
            *(float4*)&C[(size_t)row * N + col] = v;
        }
    }
}

// ---------------------------------------------------------------------------
// Flash-style cross attention.
// Q: [B*LQ, DIMM] (head h at cols h*64), K/V: [B*LK, DIMM], O: [B*LQ, DIMM].
// grid = (LQ/64, NH, BATCH), block = 64 threads, one query row per thread.
// Online softmax with lazy rescale (only on new running max).
// ---------------------------------------------------------------------------
__global__ __launch_bounds__(64) void attn_kernel(
    const float* __restrict__ Q, const float* __restrict__ K,
    const float* __restrict__ V, float* __restrict__ O)
{
    __shared__ float Ks[64][64];
    __shared__ float Vs[64][64];

    const int b = blockIdx.z;
    const int h = blockIdx.y;
    const int qrow = blockIdx.x * 64 + threadIdx.x;   // 0..LQ-1
    const float scale = 0.125f;                        // 1/sqrt(64)

    const float* qptr = Q + ((size_t)(b * LQ + qrow)) * DIMM + h * DH;
    float q[DH];
#pragma unroll
    for (int d = 0; d < DH; d++) q[d] = qptr[d] * scale;

    float o[DH];
#pragma unroll
    for (int d = 0; d < DH; d++) o[d] = 0.0f;
    float m = -INFINITY;
    float l = 0.0f;

    for (int k0 = 0; k0 < LK; k0 += 64) {
        __syncthreads();
        // Cooperative load of 64 keys + 64 values (64 dims each)
        for (int i = threadIdx.x; i < 64 * 16; i += 64) {
            const int kr = i >> 4;
            const int d4 = (i & 15) << 2;
            const size_t gbase = ((size_t)(b * LK + k0 + kr)) * DIMM + h * DH + d4;
            *(float4*)&Ks[kr][d4] = *(const float4*)&K[gbase];
            *(float4*)&Vs[kr][d4] = *(const float4*)&V[gbase];
        }
        __syncthreads();

#pragma unroll 1
        for (int kk = 0; kk < 64; kk++) {
            float s = 0.0f;
#pragma unroll
            for (int d = 0; d < DH; d++) s = fmaf(q[d], Ks[kk][d], s);

            if (s > m) {  // rare after warmup: ~O(log) per row
                const float corr = __expf(m - s);
                m = s;
                l *= corr;
#pragma unroll
                for (int d = 0; d < DH; d++) o[d] *= corr;
            }
            const float p = __expf(s - m);
            l += p;
#pragma unroll
            for (int d = 0; d < DH; d++) o[d] = fmaf(p, Vs[kk][d], o[d]);
        }
    }

    const float inv = 1.0f / l;
    float* optr = O + ((size_t)(b * LQ + qrow)) * DIMM + h * DH;
#pragma unroll
    for (int d = 0; d < DH; d++) optr[d] = o[d] * inv;
}

// ---------------------------------------------------------------------------
// Launch sequence (graph-capturable: kernel launches only)
// ---------------------------------------------------------------------------
extern "C" void kernel_launch(void* const* d_in, const int* in_sizes, int n_in,
                              void* d_out, int out_size)
{
    const float* x   = (const float*)d_in[0];
    const float* ctx = (const float*)d_in[1];
    const float* Wq  = (const float*)d_in[2];
    const float* Wk  = (const float*)d_in[3];
    const float* Wv  = (const float*)d_in[4];
    const float* Wo  = (const float*)d_in[5];
    const float* bo  = (const float*)d_in[6];
    const float* W1  = (const float*)d_in[7];
    const float* b1  = (const float*)d_in[8];
    const float* W2  = (const float*)d_in[9];
    const float* b2  = (const float*)d_in[10];
    float* out = (float*)d_out;

    float *Q, *K, *V, *O, *X1, *Hf;
    cudaGetSymbolAddress((void**)&Q,  g_Q);
    cudaGetSymbolAddress((void**)&K,  g_K);
    cudaGetSymbolAddress((void**)&V,  g_V);
    cudaGetSymbolAddress((void**)&O,  g_O);
    cudaGetSymbolAddress((void**)&X1, g_X1);
    cudaGetSymbolAddress((void**)&Hf, g_Hf);

    const dim3 blk(256);

    // Projections: Q = x@Wq, K = ctx@Wk, V = ctx@Wv
    sgemm_kernel<0><<<dim3(DIMM / 128, MQ / 128), blk>>>(x,   Wq, nullptr, nullptr, Q, MQ, DIMM, DIMM);
    sgemm_kernel<0><<<dim3(DIMM / 128, MC / 128), blk>>>(ctx, Wk, nullptr, nullptr, K, MC, DIMM, DIMM);
    sgemm_kernel<0><<<dim3(DIMM / 128, MC / 128), blk>>>(ctx, Wv, nullptr, nullptr, V, MC, DIMM, DIMM);

    // Cross attention -> O
    attn_kernel<<<dim3(LQ / 64, NH, BATCH), 64>>>(Q, K, V, O);

    // X1 = O@Wo + bo + x
    sgemm_kernel<1><<<dim3(DIMM / 128, MQ / 128), blk>>>(O, Wo, bo, x, X1, MQ, DIMM, DIMM);

    // Hf = gelu(X1@W1 + b1)
    sgemm_kernel<2><<<dim3(FF / 128, MQ / 128), blk>>>(X1, W1, b1, nullptr, Hf, MQ, FF, DIMM);

    // out = Hf@W2 + b2 + X1
    sgemm_kernel<1><<<dim3(DIMM / 128, MQ / 128), blk>>>(Hf, W2, b2, X1, out, MQ, DIMM, FF);
}

// round 3
// speedup vs baseline: 2.2763x; 2.2763x over previous
#include <cuda_runtime.h>
#include <cuda_fp16.h>
#include <cstdint>
#include <math.h>

// ---------------------------------------------------------------------------
// Problem constants
// ---------------------------------------------------------------------------
#define BATCH 4
#define LQ 1024
#define LK 2048
#define DIMM 1024
#define NH 16
#define DH 64
#define FF 4096

#define MQ (BATCH * LQ)   // 4096 query rows
#define MC (BATCH * LK)   // 8192 context rows

// ---------------------------------------------------------------------------
// Scratch (__device__ globals; allocation-free rule)
// ---------------------------------------------------------------------------
__device__ float  g_Q [MQ * DIMM];
__device__ float  g_K [MC * DIMM];
__device__ float  g_V [MC * DIMM];
__device__ float  g_X1[MQ * DIMM];

__device__ __half g_x16 [MQ * DIMM];
__device__ __half g_c16 [MC * DIMM];
__device__ __half g_O16 [MQ * DIMM];
__device__ __half g_X116[MQ * DIMM];
__device__ __half g_Hf16[MQ * FF];

__device__ __half g_WqT[DIMM * DIMM];   // [N,K]
__device__ __half g_WkT[DIMM * DIMM];
__device__ __half g_WvT[DIMM * DIMM];
__device__ __half g_WoT[DIMM * DIMM];
__device__ __half g_W1T[FF * DIMM];     // [4096, 1024]
__device__ __half g_W2T[DIMM * FF];     // [1024, 4096]

// ---------------------------------------------------------------------------
// Helpers
// ---------------------------------------------------------------------------
__device__ __forceinline__ uint32_t smem_u32(const void* p) {
    uint32_t a;
    asm("{ .reg .u64 t; cvta.to.shared.u64 t, %1; cvt.u32.u64 %0, t; }"
        : "=r"(a) : "l"(p));
    return a;
}

__device__ __forceinline__ void ldsm_x4(uint32_t* r, uint32_t addr) {
    asm volatile("ldmatrix.sync.aligned.m8n8.x4.shared.b16 {%0,%1,%2,%3}, [%4];"
                 : "=r"(r[0]), "=r"(r[1]), "=r"(r[2]), "=r"(r[3]) : "r"(addr));
}
__device__ __forceinline__ void ldsm_x2(uint32_t* r, uint32_t addr) {
    asm volatile("ldmatrix.sync.aligned.m8n8.x2.shared.b16 {%0,%1}, [%2];"
                 : "=r"(r[0]), "=r"(r[1]) : "r"(addr));
}

// D = A(16x16,row) * B(16x8,col) + D, fp16 in, fp32 accum
__device__ __forceinline__ void mma16816(float* c, const uint32_t* a, const uint32_t* b) {
    asm volatile(
        "mma.sync.aligned.m16n8k16.row.col.f32.f16.f16.f32 "
        "{%0,%1,%2,%3}, {%4,%5,%6,%7}, {%8,%9}, {%0,%1,%2,%3};"
        : "+f"(c[0]), "+f"(c[1]), "+f"(c[2]), "+f"(c[3])
        : "r"(a[0]), "r"(a[1]), "r"(a[2]), "r"(a[3]), "r"(b[0]), "r"(b[1]));
}

__device__ __forceinline__ float gelu_exact(float x) {
    return 0.5f * x * (1.0f + erff(x * 0.70710678118654752f));
}

// ---------------------------------------------------------------------------
// Conversion / transpose kernels
// ---------------------------------------------------------------------------
__global__ void cvt_f32_f16(const float4* __restrict__ src, __half2* __restrict__ dst, int n4) {
    int i = blockIdx.x * blockDim.x + threadIdx.x;
    if (i < n4) {
        float4 v = src[i];
        dst[2 * i]     = __floats2half2_rn(v.x, v.y);
        dst[2 * i + 1] = __floats2half2_rn(v.z, v.w);
    }
}

// WT[n,k] = (half) W[k,n]
__global__ void transpose_cvt(const float* __restrict__ W, __half* __restrict__ WT,
                              int K, int N) {
    __shared__ float t[32][33];
    const int n0 = blockIdx.x * 32, k0 = blockIdx.y * 32;
    const int tx = threadIdx.x, ty = threadIdx.y;
#pragma unroll
    for (int j = 0; j < 32; j += 8)
        t[ty + j][tx] = W[(size_t)(k0 + ty + j) * N + n0 + tx];
    __syncthreads();
#pragma unroll
    for (int j = 0; j < 32; j += 8)
        WT[(size_t)(n0 + ty + j) * K + k0 + tx] = __float2half(t[tx][ty + j]);
}

// ---------------------------------------------------------------------------
// HMMA fp16 GEMM: C[M,N] = A[M,K] @ B^T, B = WT[N,K]. Both K-major fp16.
// CTA 128x128, BK=32, 256 threads (8 warps, warp tile 64x32), double-buffered.
// SMEM rows padded to 40 halves (80B): ldmatrix phases hit 8 distinct banks.
// EPI: 0 = fp32 out ; 1 = bias+res -> fp32 AND fp16 ; 2 = gelu(acc+bias) -> fp16 ;
//      3 = bias+res -> fp32
// ---------------------------------------------------------------------------
#define PADK 40

template <int EPI>
__global__ __launch_bounds__(256) void tc_gemm(
    const __half* __restrict__ A, const __half* __restrict__ B,
    const float* __restrict__ bias, const float* __restrict__ res,
    float* __restrict__ C32, __half* __restrict__ C16,
    int M, int N, int K)
{
    __shared__ __half As[2][128][PADK];
    __shared__ __half Bs[2][128][PADK];

    const int tid  = threadIdx.x;
    const int warp = tid >> 5;
    const int lane = tid & 31;
    const int warpM = warp & 1;            // 0..1
    const int warpN = warp >> 1;           // 0..3
    const int wm0 = warpM * 64;
    const int wn0 = warpN * 32;

    const int rowBase = blockIdx.y * 128;
    const int colBase = blockIdx.x * 128;
    const __half* Atile = A + (size_t)rowBase * K;
    const __half* Btile = B + (size_t)colBase * K;

    // global loaders: 2 uint4 per thread per tile (128 rows x 32 halves)
    const int ldRow0 = tid >> 2;           // 0..63
    const int ldSeg  = (tid & 3) * 8;      // halves offset: 0,8,16,24

    const uint32_t asBase = smem_u32(&As[0][0][0]);
    const uint32_t bsBase = smem_u32(&Bs[0][0][0]);
    const uint32_t bufStride = 128 * PADK * 2;   // bytes per buffer

    // ldmatrix lane addressing
    const int aRow = (lane & 15);
    const int aCol = (lane >> 4) * 8;
    const int bRow = (lane & 7);
    const int bCol = ((lane >> 3) & 1) * 8;

    float c[4][4][4];
#pragma unroll
    for (int mi = 0; mi < 4; mi++)
#pragma unroll
        for (int ni = 0; ni < 4; ni++)
#pragma unroll
            for (int j = 0; j < 4; j++) c[mi][ni][j] = 0.0f;

    const int numK = K >> 5;

    // preload tile 0
    {
#pragma unroll
        for (int i = 0; i < 2; i++) {
            const int row = ldRow0 + i * 64;
            uint4 va = *(const uint4*)(Atile + (size_t)row * K + ldSeg);
            uint4 vb = *(const uint4*)(Btile + (size_t)row * K + ldSeg);
            *(uint4*)&As[0][row][ldSeg] = va;
            *(uint4*)&Bs[0][row][ldSeg] = vb;
        }
    }
    __syncthreads();

    for (int kt = 0; kt < numK; kt++) {
        const int p = kt & 1;
        uint4 ra[2], rb[2];
        if (kt + 1 < numK) {
            const int k0 = (kt + 1) * 32;
#pragma unroll
            for (int i = 0; i < 2; i++) {
                const int row = ldRow0 + i * 64;
                ra[i] = *(const uint4*)(Atile + (size_t)row * K + k0 + ldSeg);
                rb[i] = *(const uint4*)(Btile + (size_t)row * K + k0 + ldSeg);
            }
        }

        // compute on buffer p
        const uint32_t aBuf = asBase + p * bufStride;
        const uint32_t bBuf = bsBase + p * bufStride;
#pragma unroll
        for (int ks = 0; ks < 2; ks++) {
            uint32_t af[4][4], bf[4][2];
#pragma unroll
            for (int mi = 0; mi < 4; mi++)
                ldsm_x4(af[mi], aBuf + (uint32_t)((wm0 + mi * 16 + aRow) * PADK + ks * 16 + aCol) * 2);
#pragma unroll
            for (int ni = 0; ni < 4; ni++)
                ldsm_x2(bf[ni], bBuf + (uint32_t)((wn0 + ni * 8 + bRow) * PADK + ks * 16 + bCol) * 2);
#pragma unroll
            for (int mi = 0; mi < 4; mi++)
#pragma unroll
                for (int ni = 0; ni < 4; ni++)
                    mma16816(c[mi][ni], af[mi], bf[ni]);
        }

        if (kt + 1 < numK) {
            const int pn = 1 - p;
#pragma unroll
            for (int i = 0; i < 2; i++) {
                const int row = ldRow0 + i * 64;
                *(uint4*)&As[pn][row][ldSeg] = ra[i];
                *(uint4*)&Bs[pn][row][ldSeg] = rb[i];
            }
            __syncthreads();
        }
    }

    // ------------------------------------------------------------------ epi
    const int g  = lane >> 2;
    const int th = (lane & 3) * 2;
#pragma unroll
    for (int mi = 0; mi < 4; mi++) {
#pragma unroll
        for (int half = 0; half < 2; half++) {
            const int row = rowBase + wm0 + mi * 16 + g + half * 8;
#pragma unroll
            for (int ni = 0; ni < 4; ni++) {
                const int col = colBase + wn0 + ni * 8 + th;
                float v0 = c[mi][ni][half * 2 + 0];
                float v1 = c[mi][ni][half * 2 + 1];
                if (EPI == 1 || EPI == 3) {
                    v0 += bias[col]     + res[(size_t)row * N + col];
                    v1 += bias[col + 1] + res[(size_t)row * N + col + 1];
                } else if (EPI == 2) {
                    v0 = gelu_exact(v0 + bias[col]);
                    v1 = gelu_exact(v1 + bias[col + 1]);
                }
                if (EPI == 0 || EPI == 1 || EPI == 3)
                    *(float2*)&C32[(size_t)row * N + col] = make_float2(v0, v1);
                if (EPI == 1 || EPI == 2)
                    *(__half2*)&C16[(size_t)row * N + col] = __floats2half2_rn(v0, v1);
            }
        }
    }
}

// ---------------------------------------------------------------------------
// Flash-style cross attention (fp32 SIMT) + fp16 dual output.
// float4 SMEM loads, 4-way split QK accumulator (shorter dependency chains).
// ---------------------------------------------------------------------------
__global__ __launch_bounds__(64) void attn_kernel(
    const float* __restrict__ Q, const float* __restrict__ K,
    const float* __restrict__ V, float* __restrict__ O, __half* __restrict__ O16)
{
    __shared__ float Ks[64][64];
    __shared__ float Vs[64][64];

    const int b = blockIdx.z;
    const int h = blockIdx.y;
    const int qrow = blockIdx.x * 64 + threadIdx.x;
    const float scale = 0.125f;

    const float* qptr = Q + ((size_t)(b * LQ + qrow)) * DIMM + h * DH;
    float q[DH];
#pragma unroll
    for (int d = 0; d < DH; d++) q[d] = qptr[d] * scale;

    float o[DH];
#pragma unroll
    for (int d = 0; d < DH; d++) o[d] = 0.0f;
    float m = -INFINITY;
    float l = 0.0f;

    for (int k0 = 0; k0 < LK; k0 += 64) {
        __syncthreads();
        for (int i = threadIdx.x; i < 64 * 16; i += 64) {
            const int kr = i >> 4;
            const int d4 = (i & 15) << 2;
            const size_t gb = ((size_t)(b * LK + k0 + kr)) * DIMM + h * DH + d4;
            *(float4*)&Ks[kr][d4] = *(const float4*)&K[gb];
            *(float4*)&Vs[kr][d4] = *(const float4*)&V[gb];
        }
        __syncthreads();

#pragma unroll 1
        for (int kk = 0; kk < 64; kk++) {
            float s0 = 0.f, s1 = 0.f, s2 = 0.f, s3 = 0.f;
#pragma unroll
            for (int d4 = 0; d4 < 16; d4++) {
                const float4 kv = *(const float4*)&Ks[kk][d4 * 4];
                s0 = fmaf(q[d4 * 4 + 0], kv.x, s0);
                s1 = fmaf(q[d4 * 4 + 1], kv.y, s1);
                s2 = fmaf(q[d4 * 4 + 2], kv.z, s2);
                s3 = fmaf(q[d4 * 4 + 3], kv.w, s3);
            }
            const float s = (s0 + s1) + (s2 + s3);
            if (s > m) {
                const float corr = __expf(m - s);
                m = s;
                l *= corr;
#pragma unroll
                for (int d = 0; d < DH; d++) o[d] *= corr;
            }
            const float p = __expf(s - m);
            l += p;
#pragma unroll
            for (int d4 = 0; d4 < 16; d4++) {
                const float4 vv = *(const float4*)&Vs[kk][d4 * 4];
                o[d4 * 4 + 0] = fmaf(p, vv.x, o[d4 * 4 + 0]);
                o[d4 * 4 + 1] = fmaf(p, vv.y, o[d4 * 4 + 1]);
                o[d4 * 4 + 2] = fmaf(p, vv.z, o[d4 * 4 + 2]);
                o[d4 * 4 + 3] = fmaf(p, vv.w, o[d4 * 4 + 3]);
            }
        }
    }

    const float inv = 1.0f / l;
    const size_t base = ((size_t)(b * LQ + qrow)) * DIMM + h * DH;
    __half* optr16 = O16 + base;
#pragma unroll
    for (int d = 0; d < DH; d++) optr16[d] = __float2half(o[d] * inv);
}

// ---------------------------------------------------------------------------
// Launch sequence (graph-capturable: kernel launches only)
// ---------------------------------------------------------------------------
extern "C" void kernel_launch(void* const* d_in, const int* in_sizes, int n_in,
                              void* d_out, int out_size)
{
    const float* x   = (const float*)d_in[0];
    const float* ctx = (const float*)d_in[1];
    const float* Wq  = (const float*)d_in[2];
    const float* Wk  = (const float*)d_in[3];
    const float* Wv  = (const float*)d_in[4];
    const float* Wo  = (const float*)d_in[5];
    const float* bo  = (const float*)d_in[6];
    const float* W1  = (const float*)d_in[7];
    const float* b1  = (const float*)d_in[8];
    const float* W2  = (const float*)d_in[9];
    const float* b2  = (const float*)d_in[10];
    float* out = (float*)d_out;

    float *Q, *K, *V, *X1;
    __half *x16, *c16, *O16, *X116, *Hf16, *WqT, *WkT, *WvT, *WoT, *W1T, *W2T;
    cudaGetSymbolAddress((void**)&Q,    g_Q);
    cudaGetSymbolAddress((void**)&K,    g_K);
    cudaGetSymbolAddress((void**)&V,    g_V);
    cudaGetSymbolAddress((void**)&X1,   g_X1);
    cudaGetSymbolAddress((void**)&x16,  g_x16);
    cudaGetSymbolAddress((void**)&c16,  g_c16);
    cudaGetSymbolAddress((void**)&O16,  g_O16);
    cudaGetSymbolAddress((void**)&X116, g_X116);
    cudaGetSymbolAddress((void**)&Hf16, g_Hf16);
    cudaGetSymbolAddress((void**)&WqT,  g_WqT);
    cudaGetSymbolAddress((void**)&WkT,  g_WkT);
    cudaGetSymbolAddress((void**)&WvT,  g_WvT);
    cudaGetSymbolAddress((void**)&WoT,  g_WoT);
    cudaGetSymbolAddress((void**)&W1T,  g_W1T);
    cudaGetSymbolAddress((void**)&W2T,  g_W2T);

    // Convert activations to fp16 (A operands)
    cvt_f32_f16<<<(MQ * DIMM / 4 + 255) / 256, 256>>>((const float4*)x,   (__half2*)x16, MQ * DIMM / 4);
    cvt_f32_f16<<<(MC * DIMM / 4 + 255) / 256, 256>>>((const float4*)ctx, (__half2*)c16, MC * DIMM / 4);

    // Transpose+convert weights to [N,K] fp16
    dim3 tb(32, 8);
    transpose_cvt<<<dim3(DIMM / 32, DIMM / 32), tb>>>(Wq, WqT, DIMM, DIMM);
    transpose_cvt<<<dim3(DIMM / 32, DIMM / 32), tb>>>(Wk, WkT, DIMM, DIMM);
    transpose_cvt<<<dim3(DIMM / 32, DIMM / 32), tb>>>(Wv, WvT, DIMM, DIMM);
    transpose_cvt<<<dim3(DIMM / 32, DIMM / 32), tb>>>(Wo, WoT, DIMM, DIMM);
    transpose_cvt<<<dim3(FF / 32,   DIMM / 32), tb>>>(W1, W1T, DIMM, FF);
    transpose_cvt<<<dim3(DIMM / 32, FF / 32),   tb>>>(W2, W2T, FF, DIMM);

    // Projections (fp32 out for fp32 SIMT attention)
    tc_gemm<0><<<dim3(DIMM / 128, MQ / 128), 256>>>(x16, WqT, nullptr, nullptr, Q, nullptr, MQ, DIMM, DIMM);
    tc_gemm<0><<<dim3(DIMM / 128, MC / 128), 256>>>(c16, WkT, nullptr, nullptr, K, nullptr, MC, DIMM, DIMM);
    tc_gemm<0><<<dim3(DIMM / 128, MC / 128), 256>>>(c16, WvT, nullptr, nullptr, V, nullptr, MC, DIMM, DIMM);

    // Cross attention -> O16 (fp16)
    attn_kernel<<<dim3(LQ / 64, NH, BATCH), 64>>>(Q, K, V, nullptr, O16);

    // X1 = O@Wo + bo + x   (fp32 master + fp16 copy)
    tc_gemm<1><<<dim3(DIMM / 128, MQ / 128), 256>>>(O16, WoT, bo, x, X1, X116, MQ, DIMM, DIMM);

    // Hf = gelu(X1@W1 + b1)   (fp16 only)
    tc_gemm<2><<<dim3(FF / 128, MQ / 128), 256>>>(X116, W1T, b1, nullptr, nullptr, Hf16, MQ, FF, DIMM);

    // out = Hf@W2 + b2 + X1   (fp32)
    tc_gemm<3><<<dim3(DIMM / 128, MQ / 128), 256>>>(Hf16, W2T, b2, X1, out, nullptr, MQ, DIMM, FF);
}

// round 4
// speedup vs baseline: 6.2847x; 2.7609x over previous
#include <cuda_runtime.h>
#include <cuda_fp16.h>
#include <cstdint>
#include <math.h>

// ---------------------------------------------------------------------------
// Problem constants
// ---------------------------------------------------------------------------
#define BATCH 4
#define LQ 1024
#define LK 2048
#define DIMM 1024
#define NH 16
#define DH 64
#define FF 4096

#define MQ (BATCH * LQ)   // 4096 query rows
#define MC (BATCH * LK)   // 8192 context rows

// ---------------------------------------------------------------------------
// Scratch (__device__ globals; allocation-free rule)
// ---------------------------------------------------------------------------
__device__ float  g_X1[MQ * DIMM];

__device__ __half g_x16 [MQ * DIMM];
__device__ __half g_c16 [MC * DIMM];
__device__ __half g_Q16 [MQ * DIMM];      // pre-scaled by 1/8
__device__ __half g_K16 [MC * DIMM];
__device__ __half g_Vt16[MC * DIMM];      // [(b*1024 + col)][kk] transposed per head
__device__ __half g_O16 [MQ * DIMM];
__device__ __half g_X116[MQ * DIMM];
__device__ __half g_Hf16[MQ * FF];

__device__ __half g_WqT[DIMM * DIMM];     // [N,K]
__device__ __half g_WkT[DIMM * DIMM];
__device__ __half g_WvT[DIMM * DIMM];
__device__ __half g_WoT[DIMM * DIMM];
__device__ __half g_W1T[FF * DIMM];
__device__ __half g_W2T[DIMM * FF];

// ---------------------------------------------------------------------------
// Helpers
// ---------------------------------------------------------------------------
__device__ __forceinline__ uint32_t smem_u32(const void* p) {
    uint32_t a;
    asm("{ .reg .u64 t; cvta.to.shared.u64 t, %1; cvt.u32.u64 %0, t; }"
        : "=r"(a) : "l"(p));
    return a;
}

__device__ __forceinline__ void ldsm_x4(uint32_t* r, uint32_t addr) {
    asm volatile("ldmatrix.sync.aligned.m8n8.x4.shared.b16 {%0,%1,%2,%3}, [%4];"
                 : "=r"(r[0]), "=r"(r[1]), "=r"(r[2]), "=r"(r[3]) : "r"(addr));
}
__device__ __forceinline__ void ldsm_x2(uint32_t* r, uint32_t addr) {
    asm volatile("ldmatrix.sync.aligned.m8n8.x2.shared.b16 {%0,%1}, [%2];"
                 : "=r"(r[0]), "=r"(r[1]) : "r"(addr));
}

// D += A(16x16,row) * B(16x8,col), fp16 in, fp32 accum
__device__ __forceinline__ void mma16816(float* c, const uint32_t* a,
                                         uint32_t b0, uint32_t b1) {
    asm volatile(
        "mma.sync.aligned.m16n8k16.row.col.f32.f16.f16.f32 "
        "{%0,%1,%2,%3}, {%4,%5,%6,%7}, {%8,%9}, {%0,%1,%2,%3};"
        : "+f"(c[0]), "+f"(c[1]), "+f"(c[2]), "+f"(c[3])
        : "r"(a[0]), "r"(a[1]), "r"(a[2]), "r"(a[3]), "r"(b0), "r"(b1));
}

__device__ __forceinline__ float gelu_exact(float x) {
    return 0.5f * x * (1.0f + erff(x * 0.70710678118654752f));
}

// ---------------------------------------------------------------------------
// Conversion / transpose kernels
// ---------------------------------------------------------------------------
__global__ void cvt_f32_f16(const float4* __restrict__ src, __half2* __restrict__ dst, int n4) {
    int i = blockIdx.x * blockDim.x + threadIdx.x;
    if (i < n4) {
        float4 v = src[i];
        dst[2 * i]     = __floats2half2_rn(v.x, v.y);
        dst[2 * i + 1] = __floats2half2_rn(v.z, v.w);
    }
}

__global__ void transpose_cvt(const float* __restrict__ W, __half* __restrict__ WT,
                              int K, int N) {
    __shared__ float t[32][33];
    const int n0 = blockIdx.x * 32, k0 = blockIdx.y * 32;
    const int tx = threadIdx.x, ty = threadIdx.y;
#pragma unroll
    for (int j = 0; j < 32; j += 8)
        t[ty + j][tx] = W[(size_t)(k0 + ty + j) * N + n0 + tx];
    __syncthreads();
#pragma unroll
    for (int j = 0; j < 32; j += 8)
        WT[(size_t)(n0 + ty + j) * K + k0 + tx] = __float2half(t[tx][ty + j]);
}

// ---------------------------------------------------------------------------
// HMMA fp16 GEMM (as R3): C[M,N] = A[M,K] @ B^T, B = WT[N,K].
// EPI: 0 fp32 out ; 1 bias+res -> fp32+fp16 ; 2 gelu(acc+bias) -> fp16 ;
//      3 bias+res -> fp32 ; 4 fp16 out, *sc ; 5 fp16 out to Vt layout
// ---------------------------------------------------------------------------
#define PADK 40

template <int EPI>
__global__ __launch_bounds__(256) void tc_gemm(
    const __half* __restrict__ A, const __half* __restrict__ B,
    const float* __restrict__ bias, const float* __restrict__ res,
    float* __restrict__ C32, __half* __restrict__ C16,
    int M, int N, int K, float sc)
{
    __shared__ __half As[2][128][PADK];
    __shared__ __half Bs[2][128][PADK];

    const int tid  = threadIdx.x;
    const int warp = tid >> 5;
    const int lane = tid & 31;
    const int wm0 = (warp & 1) * 64;
    const int wn0 = (warp >> 1) * 32;

    const int rowBase = blockIdx.y * 128;
    const int colBase = blockIdx.x * 128;
    const __half* Atile = A + (size_t)rowBase * K;
    const __half* Btile = B + (size_t)colBase * K;

    const int ldRow0 = tid >> 2;
    const int ldSeg  = (tid & 3) * 8;

    const uint32_t asBase = smem_u32(&As[0][0][0]);
    const uint32_t bsBase = smem_u32(&Bs[0][0][0]);
    const uint32_t bufStride = 128 * PADK * 2;

    const int aRow = (lane & 15);
    const int aCol = (lane >> 4) * 8;
    const int bRow = (lane & 7);
    const int bCol = ((lane >> 3) & 1) * 8;

    float c[4][4][4];
#pragma unroll
    for (int mi = 0; mi < 4; mi++)
#pragma unroll
        for (int ni = 0; ni < 4; ni++)
#pragma unroll
            for (int j = 0; j < 4; j++) c[mi][ni][j] = 0.0f;

    const int numK = K >> 5;
    {
#pragma unroll
        for (int i = 0; i < 2; i++) {
            const int row = ldRow0 + i * 64;
            *(uint4*)&As[0][row][ldSeg] = *(const uint4*)(Atile + (size_t)row * K + ldSeg);
            *(uint4*)&Bs[0][row][ldSeg] = *(const uint4*)(Btile + (size_t)row * K + ldSeg);
        }
    }
    __syncthreads();

    for (int kt = 0; kt < numK; kt++) {
        const int p = kt & 1;
        uint4 ra[2], rb[2];
        if (kt + 1 < numK) {
            const int k0 = (kt + 1) * 32;
#pragma unroll
            for (int i = 0; i < 2; i++) {
                const int row = ldRow0 + i * 64;
                ra[i] = *(const uint4*)(Atile + (size_t)row * K + k0 + ldSeg);
                rb[i] = *(const uint4*)(Btile + (size_t)row * K + k0 + ldSeg);
            }
        }

        const uint32_t aBuf = asBase + p * bufStride;
        const uint32_t bBuf = bsBase + p * bufStride;
#pragma unroll
        for (int ks = 0; ks < 2; ks++) {
            uint32_t af[4][4], bf[4][2];
#pragma unroll
            for (int mi = 0; mi < 4; mi++)
                ldsm_x4(af[mi], aBuf + (uint32_t)((wm0 + mi * 16 + aRow) * PADK + ks * 16 + aCol) * 2);
#pragma unroll
            for (int ni = 0; ni < 4; ni++)
                ldsm_x2(bf[ni], bBuf + (uint32_t)((wn0 + ni * 8 + bRow) * PADK + ks * 16 + bCol) * 2);
#pragma unroll
            for (int mi = 0; mi < 4; mi++)
#pragma unroll
                for (int ni = 0; ni < 4; ni++)
                    mma16816(c[mi][ni], af[mi], bf[ni][0], bf[ni][1]);
        }

        if (kt + 1 < numK) {
            const int pn = 1 - p;
#pragma unroll
            for (int i = 0; i < 2; i++) {
                const int row = ldRow0 + i * 64;
                *(uint4*)&As[pn][row][ldSeg] = ra[i];
                *(uint4*)&Bs[pn][row][ldSeg] = rb[i];
            }
            __syncthreads();
        }
    }

    const int g  = lane >> 2;
    const int th = (lane & 3) * 2;
#pragma unroll
    for (int mi = 0; mi < 4; mi++) {
#pragma unroll
        for (int half = 0; half < 2; half++) {
            const int row = rowBase + wm0 + mi * 16 + g + half * 8;
#pragma unroll
            for (int ni = 0; ni < 4; ni++) {
                const int col = colBase + wn0 + ni * 8 + th;
                float v0 = c[mi][ni][half * 2 + 0];
                float v1 = c[mi][ni][half * 2 + 1];
                if (EPI == 1 || EPI == 3) {
                    v0 += bias[col]     + res[(size_t)row * N + col];
                    v1 += bias[col + 1] + res[(size_t)row * N + col + 1];
                } else if (EPI == 2) {
                    v0 = gelu_exact(v0 + bias[col]);
                    v1 = gelu_exact(v1 + bias[col + 1]);
                } else if (EPI == 4) {
                    v0 *= sc; v1 *= sc;
                }
                if (EPI == 0 || EPI == 1 || EPI == 3)
                    *(float2*)&C32[(size_t)row * N + col] = make_float2(v0, v1);
                if (EPI == 1 || EPI == 2 || EPI == 4)
                    *(__half2*)&C16[(size_t)row * N + col] = __floats2half2_rn(v0, v1);
                if (EPI == 5) {
                    // Vt[(b*1024 + col)][kk], b = row>>11, kk = row & 2047
                    const int bq = row >> 11;
                    const int kk = row & 2047;
                    C16[((size_t)(bq * 1024 + col))     * 2048 + kk] = __float2half(v0);
                    C16[((size_t)(bq * 1024 + col + 1)) * 2048 + kk] = __float2half(v1);
                }
            }
        }
    }
}

// ---------------------------------------------------------------------------
// MMA flash attention. Q16 pre-scaled by 1/8. K16 [token][dim], Vt per-head
// transposed. CTA: 64 q-rows for one (b,h); 4 warps x 16 q-rows; K-tile 64.
// ---------------------------------------------------------------------------
#define PADA 72

__global__ __launch_bounds__(128) void attn_mma(
    const __half* __restrict__ Q16, const __half* __restrict__ K16,
    const __half* __restrict__ Vt, __half* __restrict__ O16)
{
    __shared__ __half Qs[64][PADA];
    __shared__ __half Ks[64][PADA];
    __shared__ __half Vs[64][PADA];

    const int b = blockIdx.z;
    const int h = blockIdx.y;
    const int q0 = blockIdx.x * 64;
    const int tid = threadIdx.x;
    const int warp = tid >> 5;
    const int lane = tid & 31;
    const int g  = lane >> 2;
    const int th = (lane & 3) * 2;

    const uint32_t qsB = smem_u32(&Qs[0][0]);
    const uint32_t ksB = smem_u32(&Ks[0][0]);
    const uint32_t vsB = smem_u32(&Vs[0][0]);

    // load Q tile (64 rows x 64 halves of head h)
    for (int i = tid; i < 512; i += 128) {
        const int row = i >> 3, seg = (i & 7) * 8;
        *(uint4*)&Qs[row][seg] =
            *(const uint4*)&Q16[(size_t)(b * LQ + q0 + row) * DIMM + h * DH + seg];
    }

    float m0 = -INFINITY, m1 = -INFINITY, l0 = 0.f, l1 = 0.f;
    float o[8][4];
#pragma unroll
    for (int j = 0; j < 8; j++)
#pragma unroll
        for (int q = 0; q < 4; q++) o[j][q] = 0.f;

    const int aRow = lane & 15;
    const int aCol = (lane >> 4) * 8;

    for (int k0 = 0; k0 < LK; k0 += 64) {
        __syncthreads();
        for (int i = tid; i < 512; i += 128) {
            const int row = i >> 3, seg = (i & 7) * 8;
            *(uint4*)&Ks[row][seg] =
                *(const uint4*)&K16[(size_t)(b * LK + k0 + row) * DIMM + h * DH + seg];
            *(uint4*)&Vs[row][seg] =
                *(const uint4*)&Vt[((size_t)(b * 1024 + h * DH + row)) * LK + k0 + seg];
        }
        __syncthreads();

        // ---- S = Qw @ K^T : s[8 n-tiles][4]
        float s[8][4];
#pragma unroll
        for (int j = 0; j < 8; j++)
#pragma unroll
            for (int q = 0; q < 4; q++) s[j][q] = 0.f;

#pragma unroll
        for (int kc = 0; kc < 4; kc++) {
            uint32_t af[4];
            ldsm_x4(af, qsB + (uint32_t)((warp * 16 + aRow) * PADA + kc * 16 + aCol) * 2);
#pragma unroll
            for (int np = 0; np < 4; np++) {
                uint32_t bf[4];
                ldsm_x4(bf, ksB + (uint32_t)((np * 16 + aRow) * PADA + kc * 16 + aCol) * 2);
                mma16816(s[np * 2],     af, bf[0], bf[2]);
                mma16816(s[np * 2 + 1], af, bf[1], bf[3]);
            }
        }

        // ---- online softmax (rows g and g+8)
        float rm0 = s[0][0], rm1 = s[0][2];
#pragma unroll
        for (int j = 0; j < 8; j++) {
            rm0 = fmaxf(rm0, fmaxf(s[j][0], s[j][1]));
            rm1 = fmaxf(rm1, fmaxf(s[j][2], s[j][3]));
        }
        rm0 = fmaxf(rm0, __shfl_xor_sync(0xffffffffu, rm0, 1));
        rm0 = fmaxf(rm0, __shfl_xor_sync(0xffffffffu, rm0, 2));
        rm1 = fmaxf(rm1, __shfl_xor_sync(0xffffffffu, rm1, 1));
        rm1 = fmaxf(rm1, __shfl_xor_sync(0xffffffffu, rm1, 2));

        const float m0n = fmaxf(m0, rm0);
        const float m1n = fmaxf(m1, rm1);
        const float sc0 = __expf(m0 - m0n);
        const float sc1 = __expf(m1 - m1n);
        m0 = m0n; m1 = m1n;

        float ps0 = 0.f, ps1 = 0.f;
#pragma unroll
        for (int j = 0; j < 8; j++) {
            s[j][0] = __expf(s[j][0] - m0n);
            s[j][1] = __expf(s[j][1] - m0n);
            s[j][2] = __expf(s[j][2] - m1n);
            s[j][3] = __expf(s[j][3] - m1n);
            ps0 += s[j][0] + s[j][1];
            ps1 += s[j][2] + s[j][3];
        }
        l0 = l0 * sc0 + ps0;
        l1 = l1 * sc1 + ps1;
#pragma unroll
        for (int j = 0; j < 8; j++) {
            o[j][0] *= sc0; o[j][1] *= sc0;
            o[j][2] *= sc1; o[j][3] *= sc1;
        }

        // ---- pack P to fp16 A-fragments
        uint32_t ap[4][4];
#pragma unroll
        for (int kc = 0; kc < 4; kc++) {
            __half2 h0 = __floats2half2_rn(s[2 * kc][0],     s[2 * kc][1]);
            __half2 h1 = __floats2half2_rn(s[2 * kc][2],     s[2 * kc][3]);
            __half2 h2 = __floats2half2_rn(s[2 * kc + 1][0], s[2 * kc + 1][1]);
            __half2 h3 = __floats2half2_rn(s[2 * kc + 1][2], s[2 * kc + 1][3]);
            ap[kc][0] = *(uint32_t*)&h0;
            ap[kc][1] = *(uint32_t*)&h1;
            ap[kc][2] = *(uint32_t*)&h2;
            ap[kc][3] = *(uint32_t*)&h3;
        }

        // ---- O += P @ V  (B-frags from Vs[d][kk], non-trans)
#pragma unroll
        for (int kc = 0; kc < 4; kc++) {
#pragma unroll
            for (int np = 0; np < 4; np++) {
                uint32_t bv[4];
                ldsm_x4(bv, vsB + (uint32_t)((np * 16 + aRow) * PADA + kc * 16 + aCol) * 2);
                mma16816(o[np * 2],     ap[kc], bv[0], bv[2]);
                mma16816(o[np * 2 + 1], ap[kc], bv[1], bv[3]);
            }
        }
    }

    // final l reduce across quad + write
    l0 += __shfl_xor_sync(0xffffffffu, l0, 1);
    l0 += __shfl_xor_sync(0xffffffffu, l0, 2);
    l1 += __shfl_xor_sync(0xffffffffu, l1, 1);
    l1 += __shfl_xor_sync(0xffffffffu, l1, 2);
    const float inv0 = 1.0f / l0;
    const float inv1 = 1.0f / l1;

    const int row0 = b * LQ + q0 + warp * 16 + g;
#pragma unroll
    for (int j = 0; j < 8; j++) {
        const int col = h * DH + j * 8 + th;
        *(__half2*)&O16[(size_t)row0 * DIMM + col] =
            __floats2half2_rn(o[j][0] * inv0, o[j][1] * inv0);
        *(__half2*)&O16[(size_t)(row0 + 8) * DIMM + col] =
            __floats2half2_rn(o[j][2] * inv1, o[j][3] * inv1);
    }
}

// ---------------------------------------------------------------------------
// Launch sequence
// ---------------------------------------------------------------------------
extern "C" void kernel_launch(void* const* d_in, const int* in_sizes, int n_in,
                              void* d_out, int out_size)
{
    const float* x   = (const float*)d_in[0];
    const float* ctx = (const float*)d_in[1];
    const float* Wq  = (const float*)d_in[2];
    const float* Wk  = (const float*)d_in[3];
    const float* Wv  = (const float*)d_in[4];
    const float* Wo  = (const float*)d_in[5];
    const float* bo  = (const float*)d_in[6];
    const float* W1  = (const float*)d_in[7];
    const float* b1  = (const float*)d_in[8];
    const float* W2  = (const float*)d_in[9];
    const float* b2  = (const float*)d_in[10];
    float* out = (float*)d_out;

    float *X1;
    __half *x16, *c16, *Q16, *K16, *Vt16, *O16, *X116, *Hf16;
    __half *WqT, *WkT, *WvT, *WoT, *W1T, *W2T;
    cudaGetSymbolAddress((void**)&X1,   g_X1);
    cudaGetSymbolAddress((void**)&x16,  g_x16);
    cudaGetSymbolAddress((void**)&c16,  g_c16);
    cudaGetSymbolAddress((void**)&Q16,  g_Q16);
    cudaGetSymbolAddress((void**)&K16,  g_K16);
    cudaGetSymbolAddress((void**)&Vt16, g_Vt16);
    cudaGetSymbolAddress((void**)&O16,  g_O16);
    cudaGetSymbolAddress((void**)&X116, g_X116);
    cudaGetSymbolAddress((void**)&Hf16, g_Hf16);
    cudaGetSymbolAddress((void**)&WqT,  g_WqT);
    cudaGetSymbolAddress((void**)&WkT,  g_WkT);
    cudaGetSymbolAddress((void**)&WvT,  g_WvT);
    cudaGetSymbolAddress((void**)&WoT,  g_WoT);
    cudaGetSymbolAddress((void**)&W1T,  g_W1T);
    cudaGetSymbolAddress((void**)&W2T,  g_W2T);

    cvt_f32_f16<<<(MQ * DIMM / 4 + 255) / 256, 256>>>((const float4*)x,   (__half2*)x16, MQ * DIMM / 4);
    cvt_f32_f16<<<(MC * DIMM / 4 + 255) / 256, 256>>>((const float4*)ctx, (__half2*)c16, MC * DIMM / 4);

    dim3 tb(32, 8);
    transpose_cvt<<<dim3(DIMM / 32, DIMM / 32), tb>>>(Wq, WqT, DIMM, DIMM);
    transpose_cvt<<<dim3(DIMM / 32, DIMM / 32), tb>>>(Wk, WkT, DIMM, DIMM);
    transpose_cvt<<<dim3(DIMM / 32, DIMM / 32), tb>>>(Wv, WvT, DIMM, DIMM);
    transpose_cvt<<<dim3(DIMM / 32, DIMM / 32), tb>>>(Wo, WoT, DIMM, DIMM);
    transpose_cvt<<<dim3(FF / 32,   DIMM / 32), tb>>>(W1, W1T, DIMM, FF);
    transpose_cvt<<<dim3(DIMM / 32, FF / 32),   tb>>>(W2, W2T, FF, DIMM);

    // Projections -> fp16 (Q pre-scaled by 1/8; V in transposed layout)
    tc_gemm<4><<<dim3(DIMM / 128, MQ / 128), 256>>>(x16, WqT, nullptr, nullptr, nullptr, Q16,  MQ, DIMM, DIMM, 0.125f);
    tc_gemm<4><<<dim3(DIMM / 128, MC / 128), 256>>>(c16, WkT, nullptr, nullptr, nullptr, K16,  MC, DIMM, DIMM, 1.0f);
    tc_gemm<5><<<dim3(DIMM / 128, MC / 128), 256>>>(c16, WvT, nullptr, nullptr, nullptr, Vt16, MC, DIMM, DIMM, 1.0f);

    // MMA flash attention -> O16
    attn_mma<<<dim3(LQ / 64, NH, BATCH), 128>>>(Q16, K16, Vt16, O16);

    // X1 = O@Wo + bo + x
    tc_gemm<1><<<dim3(DIMM / 128, MQ / 128), 256>>>(O16, WoT, bo, x, X1, X116, MQ, DIMM, DIMM, 1.0f);

    // Hf = gelu(X1@W1 + b1)
    tc_gemm<2><<<dim3(FF / 128, MQ / 128), 256>>>(X116, W1T, b1, nullptr, nullptr, Hf16, MQ, FF, DIMM, 1.0f);

    // out = Hf@W2 + b2 + X1
    tc_gemm<3><<<dim3(DIMM / 128, MQ / 128), 256>>>(Hf16, W2T, b2, X1, out, nullptr, MQ, DIMM, FF, 1.0f);
}

// round 5
// speedup vs baseline: 6.5788x; 1.0468x over previous
#include <cuda_runtime.h>
#include <cuda_fp16.h>
#include <cstdint>
#include <math.h>

// ---------------------------------------------------------------------------
// Problem constants
// ---------------------------------------------------------------------------
#define BATCH 4
#define LQ 1024
#define LK 2048
#define DIMM 1024
#define NH 16
#define DH 64
#define FF 4096

#define MQ (BATCH * LQ)   // 4096 query rows
#define MC (BATCH * LK)   // 8192 context rows

// ---------------------------------------------------------------------------
// Scratch (__device__ globals; allocation-free rule)
// ---------------------------------------------------------------------------
__device__ float  g_X1[MQ * DIMM];

__device__ __half g_x16 [MQ * DIMM];
__device__ __half g_c16 [MC * DIMM];
__device__ __half g_Q16 [MQ * DIMM];      // pre-scaled by 1/8
__device__ __half g_K16 [MC * DIMM];
__device__ __half g_V16 [MC * DIMM];      // natural [token][dim]
__device__ __half g_O16 [MQ * DIMM];
__device__ __half g_X116[MQ * DIMM];
__device__ __half g_Hf16[MQ * FF];

__device__ __half g_WqT[DIMM * DIMM];     // [N,K]
__device__ __half g_WkT[DIMM * DIMM];
__device__ __half g_WvT[DIMM * DIMM];
__device__ __half g_WoT[DIMM * DIMM];
__device__ __half g_W1T[FF * DIMM];
__device__ __half g_W2T[DIMM * FF];

// ---------------------------------------------------------------------------
// Helpers
// ---------------------------------------------------------------------------
__device__ __forceinline__ uint32_t smem_u32(const void* p) {
    uint32_t a;
    asm("{ .reg .u64 t; cvta.to.shared.u64 t, %1; cvt.u32.u64 %0, t; }"
        : "=r"(a) : "l"(p));
    return a;
}

__device__ __forceinline__ void ldsm_x4(uint32_t* r, uint32_t addr) {
    asm volatile("ldmatrix.sync.aligned.m8n8.x4.shared.b16 {%0,%1,%2,%3}, [%4];"
                 : "=r"(r[0]), "=r"(r[1]), "=r"(r[2]), "=r"(r[3]) : "r"(addr));
}
__device__ __forceinline__ void ldsm_x4_t(uint32_t* r, uint32_t addr) {
    asm volatile("ldmatrix.sync.aligned.m8n8.x4.trans.shared.b16 {%0,%1,%2,%3}, [%4];"
                 : "=r"(r[0]), "=r"(r[1]), "=r"(r[2]), "=r"(r[3]) : "r"(addr));
}
__device__ __forceinline__ void ldsm_x2(uint32_t* r, uint32_t addr) {
    asm volatile("ldmatrix.sync.aligned.m8n8.x2.shared.b16 {%0,%1}, [%2];"
                 : "=r"(r[0]), "=r"(r[1]) : "r"(addr));
}

// D += A(16x16,row) * B(16x8,col), fp16 in, fp32 accum
__device__ __forceinline__ void mma16816(float* c, const uint32_t* a,
                                         uint32_t b0, uint32_t b1) {
    asm volatile(
        "mma.sync.aligned.m16n8k16.row.col.f32.f16.f16.f32 "
        "{%0,%1,%2,%3}, {%4,%5,%6,%7}, {%8,%9}, {%0,%1,%2,%3};"
        : "+f"(c[0]), "+f"(c[1]), "+f"(c[2]), "+f"(c[3])
        : "r"(a[0]), "r"(a[1]), "r"(a[2]), "r"(a[3]), "r"(b0), "r"(b1));
}

#define CP_ASYNC16(dst, src) \
    asm volatile("cp.async.cg.shared.global [%0], [%1], 16;" :: "r"(dst), "l"(src))
#define CP_COMMIT() asm volatile("cp.async.commit_group;" ::: "memory")
#define CP_WAIT1()  asm volatile("cp.async.wait_group 1;" ::: "memory")

__device__ __forceinline__ float gelu_exact(float x) {
    return 0.5f * x * (1.0f + erff(x * 0.70710678118654752f));
}

// ---------------------------------------------------------------------------
// Conversion / transpose kernels
// ---------------------------------------------------------------------------
__global__ void cvt_f32_f16(const float4* __restrict__ src, __half2* __restrict__ dst, int n4) {
    int i = blockIdx.x * blockDim.x + threadIdx.x;
    if (i < n4) {
        float4 v = src[i];
        dst[2 * i]     = __floats2half2_rn(v.x, v.y);
        dst[2 * i + 1] = __floats2half2_rn(v.z, v.w);
    }
}

__global__ void transpose_cvt(const float* __restrict__ W, __half* __restrict__ WT,
                              int K, int N) {
    __shared__ float t[32][33];
    const int n0 = blockIdx.x * 32, k0 = blockIdx.y * 32;
    const int tx = threadIdx.x, ty = threadIdx.y;
#pragma unroll
    for (int j = 0; j < 32; j += 8)
        t[ty + j][tx] = W[(size_t)(k0 + ty + j) * N + n0 + tx];
    __syncthreads();
#pragma unroll
    for (int j = 0; j < 32; j += 8)
        WT[(size_t)(n0 + ty + j) * K + k0 + tx] = __float2half(t[tx][ty + j]);
}

// ---------------------------------------------------------------------------
// HMMA fp16 GEMM with cp.async 3-stage pipeline.
// C[M,N] = A[M,K] @ B^T, B = WT[N,K]. CTA 128x128, BK=32, 256 threads.
// EPI: 1 bias+res -> fp32+fp16 ; 2 gelu(acc+bias) -> fp16 ;
//      3 bias+res -> fp32 ; 4 fp16 out, *sc
// ---------------------------------------------------------------------------
#define PADK 40
#define STAGES 3
#define STAGE_HALVES (128 * PADK)
#define GSMEM_BYTES (STAGES * 2 * STAGE_HALVES * 2)

template <int EPI>
__global__ __launch_bounds__(256) void tc_gemm(
    const __half* __restrict__ A, const __half* __restrict__ B,
    const float* __restrict__ bias, const float* __restrict__ res,
    float* __restrict__ C32, __half* __restrict__ C16,
    int M, int N, int K, float sc)
{
    extern __shared__ __half smh[];
    const uint32_t asBase = smem_u32(smh);
    const uint32_t bsBase = asBase + STAGES * STAGE_HALVES * 2;

    const int tid  = threadIdx.x;
    const int warp = tid >> 5;
    const int lane = tid & 31;
    const int wm0 = (warp & 1) * 64;
    const int wn0 = (warp >> 1) * 32;

    const int rowBase = blockIdx.y * 128;
    const int colBase = blockIdx.x * 128;
    const __half* Atile = A + (size_t)rowBase * K;
    const __half* Btile = B + (size_t)colBase * K;

    const int ldRow0 = tid >> 2;           // 0..63
    const int ldSeg  = (tid & 3) * 8;      // 0,8,16,24 halves

    const int aRow = (lane & 15);
    const int aCol = (lane >> 4) * 8;
    const int bRow = (lane & 7);
    const int bCol = ((lane >> 3) & 1) * 8;

    float c[4][4][4];
#pragma unroll
    for (int mi = 0; mi < 4; mi++)
#pragma unroll
        for (int ni = 0; ni < 4; ni++)
#pragma unroll
            for (int j = 0; j < 4; j++) c[mi][ni][j] = 0.0f;

    const int numK = K >> 5;

    // stage issue: 4 cp.asyncs per thread (A 2 rows, B 2 rows)
    auto issue_stage = [&](int stage, int kt) {
        const int k0 = kt * 32;
        const uint32_t ad = asBase + (uint32_t)((stage * 128 + ldRow0) * PADK + ldSeg) * 2;
        const uint32_t bd = bsBase + (uint32_t)((stage * 128 + ldRow0) * PADK + ldSeg) * 2;
        const __half* as = Atile + (size_t)ldRow0 * K + k0 + ldSeg;
        const __half* bs = Btile + (size_t)ldRow0 * K + k0 + ldSeg;
        CP_ASYNC16(ad, as);
        CP_ASYNC16(ad + 64 * PADK * 2, as + (size_t)64 * K);
        CP_ASYNC16(bd, bs);
        CP_ASYNC16(bd + 64 * PADK * 2, bs + (size_t)64 * K);
    };

    issue_stage(0, 0); CP_COMMIT();
    issue_stage(1, 1); CP_COMMIT();

    for (int kt = 0; kt < numK; kt++) {
        CP_WAIT1();
        __syncthreads();

        const int st = kt % STAGES;
        const uint32_t aBuf = asBase + (uint32_t)(st * STAGE_HALVES) * 2;
        const uint32_t bBuf = bsBase + (uint32_t)(st * STAGE_HALVES) * 2;
#pragma unroll
        for (int ks = 0; ks < 2; ks++) {
            uint32_t af[4][4], bf[4][2];
#pragma unroll
            for (int mi = 0; mi < 4; mi++)
                ldsm_x4(af[mi], aBuf + (uint32_t)((wm0 + mi * 16 + aRow) * PADK + ks * 16 + aCol) * 2);
#pragma unroll
            for (int ni = 0; ni < 4; ni++)
                ldsm_x2(bf[ni], bBuf + (uint32_t)((wn0 + ni * 8 + bRow) * PADK + ks * 16 + bCol) * 2);
#pragma unroll
            for (int mi = 0; mi < 4; mi++)
#pragma unroll
                for (int ni = 0; ni < 4; ni++)
                    mma16816(c[mi][ni], af[mi], bf[ni][0], bf[ni][1]);
        }

        const int ktn = kt + STAGES - 1;
        if (ktn < numK) issue_stage(ktn % STAGES, ktn);
        CP_COMMIT();
    }

    const int g  = lane >> 2;
    const int th = (lane & 3) * 2;
#pragma unroll
    for (int mi = 0; mi < 4; mi++) {
#pragma unroll
        for (int half = 0; half < 2; half++) {
            const int row = rowBase + wm0 + mi * 16 + g + half * 8;
#pragma unroll
            for (int ni = 0; ni < 4; ni++) {
                const int col = colBase + wn0 + ni * 8 + th;
                float v0 = c[mi][ni][half * 2 + 0];
                float v1 = c[mi][ni][half * 2 + 1];
                if (EPI == 1 || EPI == 3) {
                    v0 += bias[col]     + res[(size_t)row * N + col];
                    v1 += bias[col + 1] + res[(size_t)row * N + col + 1];
                } else if (EPI == 2) {
                    v0 = gelu_exact(v0 + bias[col]);
                    v1 = gelu_exact(v1 + bias[col + 1]);
                } else if (EPI == 4) {
                    v0 *= sc; v1 *= sc;
                }
                if (EPI == 1 || EPI == 3)
                    *(float2*)&C32[(size_t)row * N + col] = make_float2(v0, v1);
                if (EPI == 1 || EPI == 2 || EPI == 4)
                    *(__half2*)&C16[(size_t)row * N + col] = __floats2half2_rn(v0, v1);
            }
        }
    }
}

// ---------------------------------------------------------------------------
// MMA flash attention. Q16 pre-scaled by 1/8. K16/V16 [token][dim].
// CTA: 64 q-rows for one (b,h); 4 warps x 16 q-rows; K-tile 64.
// P@V B-fragments via ldmatrix.trans on natural-layout V.
// ---------------------------------------------------------------------------
#define PADA 72

__global__ __launch_bounds__(128) void attn_mma(
    const __half* __restrict__ Q16, const __half* __restrict__ K16,
    const __half* __restrict__ V16, __half* __restrict__ O16)
{
    __shared__ __half Qs[64][PADA];
    __shared__ __half Ks[64][PADA];
    __shared__ __half Vs[64][PADA];

    const int b = blockIdx.z;
    const int h = blockIdx.y;
    const int q0 = blockIdx.x * 64;
    const int tid = threadIdx.x;
    const int warp = tid >> 5;
    const int lane = tid & 31;
    const int g  = lane >> 2;
    const int th = (lane & 3) * 2;

    const uint32_t qsB = smem_u32(&Qs[0][0]);
    const uint32_t ksB = smem_u32(&Ks[0][0]);
    const uint32_t vsB = smem_u32(&Vs[0][0]);

    for (int i = tid; i < 512; i += 128) {
        const int row = i >> 3, seg = (i & 7) * 8;
        *(uint4*)&Qs[row][seg] =
            *(const uint4*)&Q16[(size_t)(b * LQ + q0 + row) * DIMM + h * DH + seg];
    }

    float m0 = -INFINITY, m1 = -INFINITY, l0 = 0.f, l1 = 0.f;
    float o[8][4];
#pragma unroll
    for (int j = 0; j < 8; j++)
#pragma unroll
        for (int q = 0; q < 4; q++) o[j][q] = 0.f;

    const int aRow = lane & 15;
    const int aCol = (lane >> 4) * 8;
    // trans-load lane addressing for V (4 matrices per x4)
    const int vq = lane >> 3;          // matrix index 0..3
    const int vi = lane & 7;           // row within matrix
    const int vTokOff = (vq & 1) * 8 + vi;   // token offset within 16-chunk
    const int vDimOff = (vq >> 1) * 8;       // dim offset within 16-dim pair

    for (int k0 = 0; k0 < LK; k0 += 64) {
        __syncthreads();
        for (int i = tid; i < 512; i += 128) {
            const int row = i >> 3, seg = (i & 7) * 8;
            *(uint4*)&Ks[row][seg] =
                *(const uint4*)&K16[(size_t)(b * LK + k0 + row) * DIMM + h * DH + seg];
            *(uint4*)&Vs[row][seg] =
                *(const uint4*)&V16[(size_t)(b * LK + k0 + row) * DIMM + h * DH + seg];
        }
        __syncthreads();

        // ---- S = Qw @ K^T
        float s[8][4];
#pragma unroll
        for (int j = 0; j < 8; j++)
#pragma unroll
            for (int q = 0; q < 4; q++) s[j][q] = 0.f;

#pragma unroll
        for (int kc = 0; kc < 4; kc++) {
            uint32_t af[4];
            ldsm_x4(af, qsB + (uint32_t)((warp * 16 + aRow) * PADA + kc * 16 + aCol) * 2);
#pragma unroll
            for (int np = 0; np < 4; np++) {
                uint32_t bf[4];
                ldsm_x4(bf, ksB + (uint32_t)((np * 16 + aRow) * PADA + kc * 16 + aCol) * 2);
                mma16816(s[np * 2],     af, bf[0], bf[2]);
                mma16816(s[np * 2 + 1], af, bf[1], bf[3]);
            }
        }

        // ---- online softmax (rows g and g+8)
        float rm0 = s[0][0], rm1 = s[0][2];
#pragma unroll
        for (int j = 0; j < 8; j++) {
            rm0 = fmaxf(rm0, fmaxf(s[j][0], s[j][1]));
            rm1 = fmaxf(rm1, fmaxf(s[j][2], s[j][3]));
        }
        rm0 = fmaxf(rm0, __shfl_xor_sync(0xffffffffu, rm0, 1));
        rm0 = fmaxf(rm0, __shfl_xor_sync(0xffffffffu, rm0, 2));
        rm1 = fmaxf(rm1, __shfl_xor_sync(0xffffffffu, rm1, 1));
        rm1 = fmaxf(rm1, __shfl_xor_sync(0xffffffffu, rm1, 2));

        const float m0n = fmaxf(m0, rm0);
        const float m1n = fmaxf(m1, rm1);
        const float sc0 = __expf(m0 - m0n);
        const float sc1 = __expf(m1 - m1n);
        m0 = m0n; m1 = m1n;

        float ps0 = 0.f, ps1 = 0.f;
#pragma unroll
        for (int j = 0; j < 8; j++) {
            s[j][0] = __expf(s[j][0] - m0n);
            s[j][1] = __expf(s[j][1] - m0n);
            s[j][2] = __expf(s[j][2] - m1n);
            s[j][3] = __expf(s[j][3] - m1n);
            ps0 += s[j][0] + s[j][1];
            ps1 += s[j][2] + s[j][3];
        }
        l0 = l0 * sc0 + ps0;
        l1 = l1 * sc1 + ps1;
#pragma unroll
        for (int j = 0; j < 8; j++) {
            o[j][0] *= sc0; o[j][1] *= sc0;
            o[j][2] *= sc1; o[j][3] *= sc1;
        }

        // ---- pack P to fp16 A-fragments
        uint32_t ap[4][4];
#pragma unroll
        for (int kc = 0; kc < 4; kc++) {
            __half2 h0 = __floats2half2_rn(s[2 * kc][0],     s[2 * kc][1]);
            __half2 h1 = __floats2half2_rn(s[2 * kc][2],     s[2 * kc][3]);
            __half2 h2 = __floats2half2_rn(s[2 * kc + 1][0], s[2 * kc + 1][1]);
            __half2 h3 = __floats2half2_rn(s[2 * kc + 1][2], s[2 * kc + 1][3]);
            ap[kc][0] = *(uint32_t*)&h0;
            ap[kc][1] = *(uint32_t*)&h1;
            ap[kc][2] = *(uint32_t*)&h2;
            ap[kc][3] = *(uint32_t*)&h3;
        }

        // ---- O += P @ V  (trans-loaded B fragments from natural V)
#pragma unroll
        for (int kc = 0; kc < 4; kc++) {
#pragma unroll
            for (int nt2 = 0; nt2 < 4; nt2++) {
                uint32_t bv[4];
                const int token = kc * 16 + vTokOff;
                const int dim   = nt2 * 16 + vDimOff;
                ldsm_x4_t(bv, vsB + (uint32_t)(token * PADA + dim) * 2);
                mma16816(o[nt2 * 2],     ap[kc], bv[0], bv[1]);
                mma16816(o[nt2 * 2 + 1], ap[kc], bv[2], bv[3]);
            }
        }
    }

    l0 += __shfl_xor_sync(0xffffffffu, l0, 1);
    l0 += __shfl_xor_sync(0xffffffffu, l0, 2);
    l1 += __shfl_xor_sync(0xffffffffu, l1, 1);
    l1 += __shfl_xor_sync(0xffffffffu, l1, 2);
    const float inv0 = 1.0f / l0;
    const float inv1 = 1.0f / l1;

    const int row0 = b * LQ + q0 + warp * 16 + g;
#pragma unroll
    for (int j = 0; j < 8; j++) {
        const int col = h * DH + j * 8 + th;
        *(__half2*)&O16[(size_t)row0 * DIMM + col] =
            __floats2half2_rn(o[j][0] * inv0, o[j][1] * inv0);
        *(__half2*)&O16[(size_t)(row0 + 8) * DIMM + col] =
            __floats2half2_rn(o[j][2] * inv1, o[j][3] * inv1);
    }
}

// ---------------------------------------------------------------------------
// Launch sequence
// ---------------------------------------------------------------------------
extern "C" void kernel_launch(void* const* d_in, const int* in_sizes, int n_in,
                              void* d_out, int out_size)
{
    const float* x   = (const float*)d_in[0];
    const float* ctx = (const float*)d_in[1];
    const float* Wq  = (const float*)d_in[2];
    const float* Wk  = (const float*)d_in[3];
    const float* Wv  = (const float*)d_in[4];
    const float* Wo  = (const float*)d_in[5];
    const float* bo  = (const float*)d_in[6];
    const float* W1  = (const float*)d_in[7];
    const float* b1  = (const float*)d_in[8];
    const float* W2  = (const float*)d_in[9];
    const float* b2  = (const float*)d_in[10];
    float* out = (float*)d_out;

    float *X1;
    __half *x16, *c16, *Q16, *K16, *V16, *O16, *X116, *Hf16;
    __half *WqT, *WkT, *WvT, *WoT, *W1T, *W2T;
    cudaGetSymbolAddress((void**)&X1,   g_X1);
    cudaGetSymbolAddress((void**)&x16,  g_x16);
    cudaGetSymbolAddress((void**)&c16,  g_c16);
    cudaGetSymbolAddress((void**)&Q16,  g_Q16);
    cudaGetSymbolAddress((void**)&K16,  g_K16);
    cudaGetSymbolAddress((void**)&V16,  g_V16);
    cudaGetSymbolAddress((void**)&O16,  g_O16);
    cudaGetSymbolAddress((void**)&X116, g_X116);
    cudaGetSymbolAddress((void**)&Hf16, g_Hf16);
    cudaGetSymbolAddress((void**)&WqT,  g_WqT);
    cudaGetSymbolAddress((void**)&WkT,  g_WkT);
    cudaGetSymbolAddress((void**)&WvT,  g_WvT);
    cudaGetSymbolAddress((void**)&WoT,  g_WoT);
    cudaGetSymbolAddress((void**)&W1T,  g_W1T);
    cudaGetSymbolAddress((void**)&W2T,  g_W2T);

    cudaFuncSetAttribute(tc_gemm<1>, cudaFuncAttributeMaxDynamicSharedMemorySize, GSMEM_BYTES);
    cudaFuncSetAttribute(tc_gemm<2>, cudaFuncAttributeMaxDynamicSharedMemorySize, GSMEM_BYTES);
    cudaFuncSetAttribute(tc_gemm<3>, cudaFuncAttributeMaxDynamicSharedMemorySize, GSMEM_BYTES);
    cudaFuncSetAttribute(tc_gemm<4>, cudaFuncAttributeMaxDynamicSharedMemorySize, GSMEM_BYTES);

    cvt_f32_f16<<<(MQ * DIMM / 4 + 255) / 256, 256>>>((const float4*)x,   (__half2*)x16, MQ * DIMM / 4);
    cvt_f32_f16<<<(MC * DIMM / 4 + 255) / 256, 256>>>((const float4*)ctx, (__half2*)c16, MC * DIMM / 4);

    dim3 tb(32, 8);
    transpose_cvt<<<dim3(DIMM / 32, DIMM / 32), tb>>>(Wq, WqT, DIMM, DIMM);
    transpose_cvt<<<dim3(DIMM / 32, DIMM / 32), tb>>>(Wk, WkT, DIMM, DIMM);
    transpose_cvt<<<dim3(DIMM / 32, DIMM / 32), tb>>>(Wv, WvT, DIMM, DIMM);
    transpose_cvt<<<dim3(DIMM / 32, DIMM / 32), tb>>>(Wo, WoT, DIMM, DIMM);
    transpose_cvt<<<dim3(FF / 32,   DIMM / 32), tb>>>(W1, W1T, DIMM, FF);
    transpose_cvt<<<dim3(DIMM / 32, FF / 32),   tb>>>(W2, W2T, FF, DIMM);

    // Projections -> fp16 (Q pre-scaled by 1/8; V natural layout)
    tc_gemm<4><<<dim3(DIMM / 128, MQ / 128), 256, GSMEM_BYTES>>>(x16, WqT, nullptr, nullptr, nullptr, Q16, MQ, DIMM, DIMM, 0.125f);
    tc_gemm<4><<<dim3(DIMM / 128, MC / 128), 256, GSMEM_BYTES>>>(c16, WkT, nullptr, nullptr, nullptr, K16, MC, DIMM, DIMM, 1.0f);
    tc_gemm<4><<<dim3(DIMM / 128, MC / 128), 256, GSMEM_BYTES>>>(c16, WvT, nullptr, nullptr, nullptr, V16, MC, DIMM, DIMM, 1.0f);

    // MMA flash attention -> O16
    attn_mma<<<dim3(LQ / 64, NH, BATCH), 128>>>(Q16, K16, V16, O16);

    // X1 = O@Wo + bo + x
    tc_gemm<1><<<dim3(DIMM / 128, MQ / 128), 256, GSMEM_BYTES>>>(O16, WoT, bo, x, X1, X116, MQ, DIMM, DIMM, 1.0f);

    // Hf = gelu(X1@W1 + b1)
    tc_gemm<2><<<dim3(FF / 128, MQ / 128), 256, GSMEM_BYTES>>>(X116, W1T, b1, nullptr, nullptr, Hf16, MQ, FF, DIMM, 1.0f);

    // out = Hf@W2 + b2 + X1
    tc_gemm<3><<<dim3(DIMM / 128, MQ / 128), 256, GSMEM_BYTES>>>(Hf16, W2T, b2, X1, out, nullptr, MQ, DIMM, FF, 1.0f);
}